// round 11
// baseline (speedup 1.0000x reference)
#include <cuda_runtime.h>
#include <cuda_bf16.h>
#include <cstdint>

// ============================ problem constants ============================
#define BB   64
#define LL   12
#define NN   883
#define DD   64
#define TT   12
#define MM   64
#define ROWS  (BB*NN)           // 56512 = 883*64 exactly
#define TILES (ROWS/16)         // 3532

// ============================ scratch ======================================
// B fragments for mma.m16n8k16 (row.col), hi/lo interleaved per uint4:
//   g_B1/g_B2[((t*8 + j)*4 + kk)*32 + lane] = { hi.x, hi.y, lo.x, lo.y }
//   .x=pack(e_k,e_k+1), .y=pack(e_k+8,e_k+9) for n=8j+lane/4, k=16kk+2*(lane%4)
// GEMM1: B[k=d][n=m] = M[t][m][d]   GEMM2: B[k=m][n=d] = M[t][m][d]
__device__ uint4 g_B1[TT * 8 * 4 * 32];
__device__ uint4 g_B2[TT * 8 * 4 * 32];

// ============================ helpers ======================================
__device__ __forceinline__ uint32_t pack_bf16(__nv_bfloat16 lo, __nv_bfloat16 hi) {
    return (uint32_t)__bfloat16_as_ushort(lo) | ((uint32_t)__bfloat16_as_ushort(hi) << 16);
}
__device__ __forceinline__ void split_bf16(float v, __nv_bfloat16& h, __nv_bfloat16& l) {
    h = __float2bfloat16_rn(v);
    l = __float2bfloat16_rn(v - __bfloat162float(h));
}
__device__ __forceinline__ uint32_t smem_u32(const void* p) {
    uint32_t a;
    asm("{ .reg .u64 t; cvta.to.shared.u64 t, %1; cvt.u32.u64 %0, t; }" : "=r"(a) : "l"(p));
    return a;
}
// D += A * B  (m16n8k16, bf16 in, fp32 accum)
__device__ __forceinline__ void mma_bf16(float* c, const uint32_t* a,
                                         uint32_t b0, uint32_t b1) {
    asm volatile(
        "mma.sync.aligned.m16n8k16.row.col.f32.bf16.bf16.f32 "
        "{%0,%1,%2,%3}, {%4,%5,%6,%7}, {%8,%9}, {%0,%1,%2,%3};"
        : "+f"(c[0]), "+f"(c[1]), "+f"(c[2]), "+f"(c[3])
        : "r"(a[0]), "r"(a[1]), "r"(a[2]), "r"(a[3]), "r"(b0), "r"(b1));
}
#define CP_COMMIT() asm volatile("cp.async.commit_group;" ::: "memory")
#define CP_WAIT(n)  asm volatile("cp.async.wait_group %0;" :: "n"(n) : "memory")

// ================= kernel 1: build lane-indexed B fragment tables ==========
// one thread per uint4: 12t * 2g * 8j * 4kk * 32lane = 24576 -> 96 x 256
__global__ __launch_bounds__(256) void ma_tables(const float* __restrict__ Mw) {
    int i = blockIdx.x * 256 + threadIdx.x;
    int lane =  i        & 31;
    int kk   = (i >> 5)  & 3;
    int j    = (i >> 7)  & 7;
    int g    = (i >> 10) & 1;
    int t    =  i >> 11;
    int nidx  = 8 * j + (lane >> 2);
    int kbase = 16 * kk + 2 * (lane & 3);
    const float* Mt = Mw + t * (MM * DD);
    float e0, e1, e2, e3;
    if (g == 0) {   // GEMM1: B[k=d][n=m] = M[m][d]
        int m = nidx;
        e0 = Mt[m * DD + kbase];
        e1 = Mt[m * DD + kbase + 1];
        e2 = Mt[m * DD + kbase + 8];
        e3 = Mt[m * DD + kbase + 9];
    } else {        // GEMM2: B[k=m][n=d] = M[m][d]
        int d = nidx;
        e0 = Mt[(kbase    ) * DD + d];
        e1 = Mt[(kbase + 1) * DD + d];
        e2 = Mt[(kbase + 8) * DD + d];
        e3 = Mt[(kbase + 9) * DD + d];
    }
    __nv_bfloat16 h0,l0,h1,l1,h2,l2,h3,l3;
    split_bf16(e0, h0, l0); split_bf16(e1, h1, l1);
    split_bf16(e2, h2, l2); split_bf16(e3, h3, l3);
    uint4 w = make_uint4(pack_bf16(h0, h1), pack_bf16(h2, h3),
                         pack_bf16(l0, l1), pack_bf16(l2, l3));
    int idx = ((t * 8 + j) * 4 + kk) * 32 + lane;
    if (g == 0) g_B1[idx] = w; else g_B2[idx] = w;
}

// ==== kernel 2: fused reduce + GEMM-softmax-GEMM, B staged via cp.async ====
// 128 threads = 4 warps; warp w owns tile blk*4+w (16 rows). 883 blocks.
__global__ __launch_bounds__(128) void ma_main(const float* __restrict__ x,
                                               float* __restrict__ out) {
    __shared__ uint4 sbuf[2][1024];   // B double-buffer, 32 KB (also phase-0 temp)
    __shared__ uint4 shAh[512];       // A-hi fragments, 8 KB
    __shared__ uint4 shAl[512];       // A-lo fragments, 8 KB

    int tid  = threadIdx.x;
    int wid  = tid >> 5;
    int lane = tid & 31;
    int qr   = lane >> 2;
    int qc   = lane & 3;

    const uint32_t sb = smem_u32(sbuf);

    // ---- phase 0: reduce x over L; row-major splits into sbuf (temp) ----
    {
        uint32_t* tmp_hi = reinterpret_cast<uint32_t*>(sbuf);          // 8 KB
        uint32_t* tmp_lo = reinterpret_cast<uint32_t*>(sbuf) + 2048;   // 8 KB
        int rl   = tid >> 1;
        int half = tid & 1;
        int row  = blockIdx.x * 64 + rl;
        int b = row / NN;
        int n = row - b * NN;
        const float* bp = x + ((size_t)b * LL * NN + n) * DD + half * 32;
        float4 av[8];
#pragma unroll
        for (int i = 0; i < 8; i++) av[i] = reinterpret_cast<const float4*>(bp)[i];
#pragma unroll
        for (int l = 1; l < LL; l++) {
            const float4* p = reinterpret_cast<const float4*>(bp + (size_t)l * NN * DD);
#pragma unroll
            for (int i = 0; i < 8; i++) {
                float4 v = p[i];
                av[i].x += v.x; av[i].y += v.y; av[i].z += v.z; av[i].w += v.w;
            }
        }
        int w = rl * 32 + half * 16;
#pragma unroll
        for (int i = 0; i < 8; i++) {
            __nv_bfloat16 hx,lx,hy,ly,hz,lz,hw,lw;
            split_bf16(av[i].x, hx, lx); split_bf16(av[i].y, hy, ly);
            split_bf16(av[i].z, hz, lz); split_bf16(av[i].w, hw, lw);
            tmp_hi[w + 2*i]     = pack_bf16(hx, hy);
            tmp_hi[w + 2*i + 1] = pack_bf16(hz, hw);
            tmp_lo[w + 2*i]     = pack_bf16(lx, ly);
            tmp_lo[w + 2*i + 1] = pack_bf16(lz, lw);
        }
    }
    __syncthreads();

    // ---- phase 1: gather fragment-major A into shA (warp w -> its tile) ----
    {
        const uint32_t* tmp_hi = reinterpret_cast<const uint32_t*>(sbuf);
        const uint32_t* tmp_lo = reinterpret_cast<const uint32_t*>(sbuf) + 2048;
        int wA = (wid * 16 + qr) * 32;
        int wB = wA + 8 * 32;
#pragma unroll
        for (int kk = 0; kk < 4; kk++) {
            int o = 8 * kk + qc;
            shAh[(wid * 4 + kk) * 32 + lane] =
                make_uint4(tmp_hi[wA + o], tmp_hi[wB + o],
                           tmp_hi[wA + o + 4], tmp_hi[wB + o + 4]);
            shAl[(wid * 4 + kk) * 32 + lane] =
                make_uint4(tmp_lo[wA + o], tmp_lo[wB + o],
                           tmp_lo[wA + o + 4], tmp_lo[wB + o + 4]);
        }
    }
    __syncthreads();   // temp dead; sbuf now free for B staging

    // async copy of phase p's 16 KB B table into its slot (8 x 16B per thread)
    auto cp_phase = [&](int p) {
        if (p < 2 * TT) {
            int t = p >> 1;
            const uint4* src = ((p & 1) ? g_B2 : g_B1) + (size_t)t * 1024 + tid;
            uint32_t dst = sb + ((uint32_t)(p & 1) * 1024 + tid) * 16;
#pragma unroll
            for (int k = 0; k < 8; k++)
                asm volatile("cp.async.cg.shared.global [%0], [%1], 16;"
                             :: "r"(dst + k * 2048), "l"(src + k * 128) : "memory");
        }
    };

    int tile = blockIdx.x * 4 + wid;
    int rA = tile * 16 + qr;
    int rB = rA + 8;
    int bA = rA / NN, nA = rA - bA * NN;
    int bB = rB / NN, nB = rB - bB * NN;
    float* outA = out + ((size_t)bA * TT * NN + nA) * DD + 2 * qc;
    float* outB = out + ((size_t)bB * TT * NN + nB) * DD + 2 * qc;

    const uint4* Ah = shAh + wid * 4 * 32 + lane;
    const uint4* Al = shAl + wid * 4 * 32 + lane;
    const uint4* S0 = &sbuf[0][lane];
    const uint4* S1 = &sbuf[1][lane];

    cp_phase(0);
    CP_COMMIT();

#pragma unroll 1
    for (int t = 0; t < TT; t++) {
        // ================= phase 2t: GEMM1 (slot 0) =================
        __syncthreads();                 // slot1 free (prev GEMM2 done)
        cp_phase(2 * t + 1);
        CP_COMMIT();
        CP_WAIT(1);                      // phase 2t resident
        __syncthreads();

        float acc[32];
#pragma unroll
        for (int i = 0; i < 32; i++) acc[i] = 0.f;
#pragma unroll
        for (int kk = 0; kk < 4; kk++) {
            uint4 a_h = Ah[kk * 32];
            uint4 a_l = Al[kk * 32];
            const uint32_t* ph = reinterpret_cast<const uint32_t*>(&a_h);
            const uint32_t* pl = reinterpret_cast<const uint32_t*>(&a_l);
#pragma unroll
            for (int j = 0; j < 8; j++) {
                uint4 b = S0[(j * 4 + kk) * 32];
                mma_bf16(&acc[4*j], ph, b.x, b.y);
                mma_bf16(&acc[4*j], pl, b.x, b.y);
                mma_bf16(&acc[4*j], ph, b.z, b.w);
            }
        }

        // ---- softmax over 64 m (rows A/B split across 4-lane quads) ----
        float mA = -1e30f, mB = -1e30f;
#pragma unroll
        for (int j = 0; j < 8; j++) {
            mA = fmaxf(mA, fmaxf(acc[4*j],   acc[4*j+1]));
            mB = fmaxf(mB, fmaxf(acc[4*j+2], acc[4*j+3]));
        }
        mA = fmaxf(mA, __shfl_xor_sync(0xffffffffu, mA, 1));
        mA = fmaxf(mA, __shfl_xor_sync(0xffffffffu, mA, 2));
        mB = fmaxf(mB, __shfl_xor_sync(0xffffffffu, mB, 1));
        mB = fmaxf(mB, __shfl_xor_sync(0xffffffffu, mB, 2));
        float sA = 0.f, sB = 0.f;
#pragma unroll
        for (int j = 0; j < 8; j++) {
            acc[4*j]   = __expf(acc[4*j]   - mA);
            acc[4*j+1] = __expf(acc[4*j+1] - mA);
            acc[4*j+2] = __expf(acc[4*j+2] - mB);
            acc[4*j+3] = __expf(acc[4*j+3] - mB);
            sA += acc[4*j] + acc[4*j+1];
            sB += acc[4*j+2] + acc[4*j+3];
        }
        sA += __shfl_xor_sync(0xffffffffu, sA, 1);
        sA += __shfl_xor_sync(0xffffffffu, sA, 2);
        sB += __shfl_xor_sync(0xffffffffu, sB, 1);
        sB += __shfl_xor_sync(0xffffffffu, sB, 2);
        float iA = 1.0f / sA, iB = 1.0f / sB;

        // ================= phase 2t+1: GEMM2 (slot 1) =================
        __syncthreads();                 // slot0 free (GEMM1 above done)
        cp_phase(2 * t + 2);
        if (t < TT - 1) { CP_COMMIT(); CP_WAIT(1); }
        else            { CP_WAIT(0); }
        __syncthreads();

        float outv[32];
#pragma unroll
        for (int i = 0; i < 32; i++) outv[i] = 0.f;
#pragma unroll
        for (int kk = 0; kk < 4; kk++) {
            int j0 = 2 * kk, j1 = 2 * kk + 1;
            uint32_t a_h[4], a_l[4];
            {
                __nv_bfloat16 h0,l0,h1,l1;
                split_bf16(acc[4*j0]   * iA, h0, l0);
                split_bf16(acc[4*j0+1] * iA, h1, l1);
                a_h[0] = pack_bf16(h0, h1); a_l[0] = pack_bf16(l0, l1);
                split_bf16(acc[4*j0+2] * iB, h0, l0);
                split_bf16(acc[4*j0+3] * iB, h1, l1);
                a_h[1] = pack_bf16(h0, h1); a_l[1] = pack_bf16(l0, l1);
                split_bf16(acc[4*j1]   * iA, h0, l0);
                split_bf16(acc[4*j1+1] * iA, h1, l1);
                a_h[2] = pack_bf16(h0, h1); a_l[2] = pack_bf16(l0, l1);
                split_bf16(acc[4*j1+2] * iB, h0, l0);
                split_bf16(acc[4*j1+3] * iB, h1, l1);
                a_h[3] = pack_bf16(h0, h1); a_l[3] = pack_bf16(l0, l1);
            }
#pragma unroll
            for (int j = 0; j < 8; j++) {
                uint4 b = S1[(j * 4 + kk) * 32];
                mma_bf16(&outv[4*j], a_h, b.x, b.y);
                mma_bf16(&outv[4*j], a_l, b.x, b.y);
                mma_bf16(&outv[4*j], a_h, b.z, b.w);
            }
        }

        // ---- store value tile (all rows valid: 56512 = 883*64) ----
        size_t tofs = (size_t)t * (NN * DD);
        float* pA = outA + tofs;
        float* pB = outB + tofs;
#pragma unroll
        for (int j = 0; j < 8; j++) {
            *reinterpret_cast<float2*>(pA + 8 * j) = make_float2(outv[4*j],   outv[4*j+1]);
            *reinterpret_cast<float2*>(pB + 8 * j) = make_float2(outv[4*j+2], outv[4*j+3]);
        }
    }
}

// ============================ launch =======================================
extern "C" void kernel_launch(void* const* d_in, const int* in_sizes, int n_in,
                              void* d_out, int out_size) {
    const float* x  = (const float*)d_in[0];
    const float* Mw = (const float*)d_in[1];
    float* out = (float*)d_out;

    ma_tables<<<96, 256>>>(Mw);
    ma_main<<<883, 128>>>(x, out);
}